// round 2
// baseline (speedup 1.0000x reference)
#include <cuda_runtime.h>

#define D 128
#define NODES_MAX 100000
#define EDGES_MAX 500000

// Scratch: precomputed node projections (sender path / receiver path).
__device__ float g_Ps[(size_t)NODES_MAX * D];
__device__ float g_Pr[(size_t)NODES_MAX * D];

// ---------------------------------------------------------------------------
// Kernel 1: node projections  P = node_attr @ W1[part]   (part 0: rows 0..127,
// part 1: rows 128..255 of W1).  Tile: 128 rows x 128 cols, 256 threads,
// 8x8 micro-tile per thread.
// ---------------------------------------------------------------------------
extern "C" __global__ void __launch_bounds__(256)
node_proj_kernel(const float* __restrict__ node_attr,
                 const float* __restrict__ W1,
                 int n_nodes)
{
    extern __shared__ float smem[];
    float* Ws = smem;           // 128*128 weights
    float* As = smem + 16384;   // 8*128 A chunk, layout [kk][row]

    const int t  = threadIdx.x;
    const int tx = t & 15, ty = t >> 4;
    const int row0  = blockIdx.x * 128;
    const int rbase = ty * 8, cbase = tx * 8;

    const float* Wsrc = W1 + (size_t)blockIdx.y * 16384;
    float* Pout = blockIdx.y ? g_Pr : g_Ps;

    #pragma unroll 4
    for (int idx = t; idx < 4096; idx += 256)
        ((float4*)Ws)[idx] = ((const float4*)Wsrc)[idx];

    float acc[8][8];
    #pragma unroll
    for (int i = 0; i < 8; i++)
        #pragma unroll
        for (int j = 0; j < 8; j++) acc[i][j] = 0.f;

    for (int k0 = 0; k0 < 128; k0 += 8) {
        // Stage A chunk: rows [row0,row0+128), k in [k0,k0+8) -> As[kk][row]
        {
            int r  = t >> 1;
            int kq = (t & 1) * 4;
            int grow = row0 + r;
            float4 v = make_float4(0.f, 0.f, 0.f, 0.f);
            if (grow < n_nodes)
                v = *(const float4*)(node_attr + (size_t)grow * D + k0 + kq);
            As[(kq + 0) * 128 + r] = v.x;
            As[(kq + 1) * 128 + r] = v.y;
            As[(kq + 2) * 128 + r] = v.z;
            As[(kq + 3) * 128 + r] = v.w;
        }
        __syncthreads();
        #pragma unroll
        for (int kk = 0; kk < 8; kk++) {
            float a[8], b[8];
            *(float4*)&a[0] = *(float4*)(As + kk * 128 + rbase);
            *(float4*)&a[4] = *(float4*)(As + kk * 128 + rbase + 4);
            *(float4*)&b[0] = *(float4*)(Ws + (k0 + kk) * 128 + cbase);
            *(float4*)&b[4] = *(float4*)(Ws + (k0 + kk) * 128 + cbase + 4);
            #pragma unroll
            for (int i = 0; i < 8; i++)
                #pragma unroll
                for (int j = 0; j < 8; j++)
                    acc[i][j] = fmaf(a[i], b[j], acc[i][j]);
        }
        __syncthreads();
    }

    #pragma unroll
    for (int i = 0; i < 8; i++) {
        int grow = row0 + rbase + i;
        if (grow < n_nodes) {
            float* o = Pout + (size_t)grow * D + cbase;
            *(float4*)(o)     = make_float4(acc[i][0], acc[i][1], acc[i][2], acc[i][3]);
            *(float4*)(o + 4) = make_float4(acc[i][4], acc[i][5], acc[i][6], acc[i][7]);
        }
    }
}

// ---------------------------------------------------------------------------
// Kernel 2: fused per-edge MLP.
//   H   = relu(edge @ W1c + Ps[s] + Pr[r] + b1)   (H tile kept in smem)
//   OUT = LayerNorm(H @ W2 + b2) * gamma + beta
// Tile: 128 edges x 128, 256 threads, 8x8 per thread. LN is block-local
// (full row of 128 lives in the block); row reduce via 16-lane shfl_xor.
// ---------------------------------------------------------------------------
extern "C" __global__ void __launch_bounds__(256)
edge_mlp_kernel(const float* __restrict__ edge_attr,
                const int*   __restrict__ senders,
                const int*   __restrict__ receivers,
                const float* __restrict__ W1,
                const float* __restrict__ b1,
                const float* __restrict__ W2,
                const float* __restrict__ b2,
                const float* __restrict__ gamma_,
                const float* __restrict__ beta_,
                float*       __restrict__ out,
                int n_edges)
{
    extern __shared__ float smem[];
    float* Ws = smem;            // 128*128 weights (W1c, then W2)
    float* Hs = smem + 16384;    // 128*128 hidden tile, row-major
    float* As = smem + 32768;    // 8*128 A chunk, layout [kk][row]

    const int t  = threadIdx.x;
    const int tx = t & 15, ty = t >> 4;
    const int row0  = blockIdx.x * 128;
    const int rbase = ty * 8, cbase = tx * 8;

    // ---- Load W1c (rows 256..383 of W1) ----
    const float* W1c = W1 + 2 * 16384;
    #pragma unroll 4
    for (int idx = t; idx < 4096; idx += 256)
        ((float4*)Ws)[idx] = ((const float4*)W1c)[idx];

    float acc[8][8];
    #pragma unroll
    for (int i = 0; i < 8; i++)
        #pragma unroll
        for (int j = 0; j < 8; j++) acc[i][j] = 0.f;

    // ---- GEMM1: edge_attr tile @ W1c ----
    for (int k0 = 0; k0 < 128; k0 += 8) {
        {
            int r  = t >> 1;
            int kq = (t & 1) * 4;
            int grow = row0 + r;
            float4 v = make_float4(0.f, 0.f, 0.f, 0.f);
            if (grow < n_edges)
                v = *(const float4*)(edge_attr + (size_t)grow * D + k0 + kq);
            As[(kq + 0) * 128 + r] = v.x;
            As[(kq + 1) * 128 + r] = v.y;
            As[(kq + 2) * 128 + r] = v.z;
            As[(kq + 3) * 128 + r] = v.w;
        }
        __syncthreads();
        #pragma unroll
        for (int kk = 0; kk < 8; kk++) {
            float a[8], b[8];
            *(float4*)&a[0] = *(float4*)(As + kk * 128 + rbase);
            *(float4*)&a[4] = *(float4*)(As + kk * 128 + rbase + 4);
            *(float4*)&b[0] = *(float4*)(Ws + (k0 + kk) * 128 + cbase);
            *(float4*)&b[4] = *(float4*)(Ws + (k0 + kk) * 128 + cbase + 4);
            #pragma unroll
            for (int i = 0; i < 8; i++)
                #pragma unroll
                for (int j = 0; j < 8; j++)
                    acc[i][j] = fmaf(a[i], b[j], acc[i][j]);
        }
        __syncthreads();
    }

    // ---- Epilogue 1: + Ps[sender] + Pr[receiver] + b1, ReLU -> Hs ----
    float b1v[8];
    *(float4*)&b1v[0] = *(const float4*)(b1 + cbase);
    *(float4*)&b1v[4] = *(const float4*)(b1 + cbase + 4);

    #pragma unroll
    for (int i = 0; i < 8; i++) {
        int grow = row0 + rbase + i;
        int si = 0, ri = 0;
        if (grow < n_edges) { si = senders[grow]; ri = receivers[grow]; }
        const float* ps = g_Ps + (size_t)si * D + cbase;
        const float* pr = g_Pr + (size_t)ri * D + cbase;
        float4 p0 = *(const float4*)(ps);
        float4 p1 = *(const float4*)(ps + 4);
        float4 q0 = *(const float4*)(pr);
        float4 q1 = *(const float4*)(pr + 4);
        float h[8];
        h[0] = fmaxf(acc[i][0] + p0.x + q0.x + b1v[0], 0.f);
        h[1] = fmaxf(acc[i][1] + p0.y + q0.y + b1v[1], 0.f);
        h[2] = fmaxf(acc[i][2] + p0.z + q0.z + b1v[2], 0.f);
        h[3] = fmaxf(acc[i][3] + p0.w + q0.w + b1v[3], 0.f);
        h[4] = fmaxf(acc[i][4] + p1.x + q1.x + b1v[4], 0.f);
        h[5] = fmaxf(acc[i][5] + p1.y + q1.y + b1v[5], 0.f);
        h[6] = fmaxf(acc[i][6] + p1.z + q1.z + b1v[6], 0.f);
        h[7] = fmaxf(acc[i][7] + p1.w + q1.w + b1v[7], 0.f);
        float* hp = Hs + (rbase + i) * 128 + cbase;
        *(float4*)(hp)     = make_float4(h[0], h[1], h[2], h[3]);
        *(float4*)(hp + 4) = make_float4(h[4], h[5], h[6], h[7]);
    }

    // ---- Swap W2 into Ws (GEMM1 Ws reads finished at last sync) ----
    #pragma unroll 4
    for (int idx = t; idx < 4096; idx += 256)
        ((float4*)Ws)[idx] = ((const float4*)W2)[idx];

    #pragma unroll
    for (int i = 0; i < 8; i++)
        #pragma unroll
        for (int j = 0; j < 8; j++) acc[i][j] = 0.f;

    __syncthreads();   // Hs + W2 visible to all

    // ---- GEMM2: Hs @ W2 ----
    for (int k0 = 0; k0 < 128; k0 += 8) {
        #pragma unroll
        for (int kk = 0; kk < 8; kk++) {
            int k = k0 + kk;
            float a[8], b[8];
            #pragma unroll
            for (int i = 0; i < 8; i++) a[i] = Hs[(rbase + i) * 128 + k];
            *(float4*)&b[0] = *(float4*)(Ws + k * 128 + cbase);
            *(float4*)&b[4] = *(float4*)(Ws + k * 128 + cbase + 4);
            #pragma unroll
            for (int i = 0; i < 8; i++)
                #pragma unroll
                for (int j = 0; j < 8; j++)
                    acc[i][j] = fmaf(a[i], b[j], acc[i][j]);
        }
    }

    // ---- Epilogue 2: +b2, LayerNorm over the 128-wide row, scale/shift ----
    float b2v[8], gv[8], bev[8];
    *(float4*)&b2v[0] = *(const float4*)(b2 + cbase);
    *(float4*)&b2v[4] = *(const float4*)(b2 + cbase + 4);
    *(float4*)&gv[0]  = *(const float4*)(gamma_ + cbase);
    *(float4*)&gv[4]  = *(const float4*)(gamma_ + cbase + 4);
    *(float4*)&bev[0] = *(const float4*)(beta_ + cbase);
    *(float4*)&bev[4] = *(const float4*)(beta_ + cbase + 4);

    #pragma unroll
    for (int i = 0; i < 8; i++) {
        float s = 0.f, ss = 0.f;
        #pragma unroll
        for (int j = 0; j < 8; j++) {
            float v = acc[i][j] + b2v[j];
            acc[i][j] = v;
            s  += v;
            ss += v * v;
        }
        // Row lives on 16 consecutive lanes (same ty within the warp half).
        #pragma unroll
        for (int off = 8; off >= 1; off >>= 1) {
            s  += __shfl_xor_sync(0xffffffffu, s,  off, 16);
            ss += __shfl_xor_sync(0xffffffffu, ss, off, 16);
        }
        float mean = s * 0.0078125f;                  // /128
        float var  = ss * 0.0078125f - mean * mean;   // biased var (jnp.var)
        float rstd = rsqrtf(var + 1e-5f);

        int grow = row0 + rbase + i;
        if (grow < n_edges) {
            float o[8];
            #pragma unroll
            for (int j = 0; j < 8; j++)
                o[j] = (acc[i][j] - mean) * rstd * gv[j] + bev[j];
            float* op = out + (size_t)grow * D + cbase;
            *(float4*)(op)     = make_float4(o[0], o[1], o[2], o[3]);
            *(float4*)(op + 4) = make_float4(o[4], o[5], o[6], o[7]);
        }
    }
}

// ---------------------------------------------------------------------------
// Launch
// ---------------------------------------------------------------------------
extern "C" void kernel_launch(void* const* d_in, const int* in_sizes, int n_in,
                              void* d_out, int out_size)
{
    const float* node_attr = (const float*)d_in[0];
    const float* edge_attr = (const float*)d_in[1];
    const int*   senders   = (const int*)d_in[2];
    const int*   receivers = (const int*)d_in[3];
    const float* W1        = (const float*)d_in[4];
    const float* b1        = (const float*)d_in[5];
    const float* W2        = (const float*)d_in[6];
    const float* b2        = (const float*)d_in[7];
    const float* gamma_    = (const float*)d_in[8];
    const float* beta_     = (const float*)d_in[9];
    float* out = (float*)d_out;

    int n_nodes = in_sizes[0] / D;
    int n_edges = in_sizes[2];

    const int SMEM1 = (16384 + 1024) * 4;            // 68 KB
    const int SMEM2 = (16384 + 16384 + 1024) * 4;    // 132 KB

    cudaFuncSetAttribute((const void*)node_proj_kernel,
                         cudaFuncAttributeMaxDynamicSharedMemorySize, SMEM1);
    cudaFuncSetAttribute((const void*)edge_mlp_kernel,
                         cudaFuncAttributeMaxDynamicSharedMemorySize, SMEM2);

    dim3 g1((n_nodes + 127) / 128, 2);
    node_proj_kernel<<<g1, 256, SMEM1>>>(node_attr, W1, n_nodes);

    dim3 g2((n_edges + 127) / 128);
    edge_mlp_kernel<<<g2, 256, SMEM2>>>(edge_attr, senders, receivers,
                                        W1, b1, W2, b2, gamma_, beta_,
                                        out, n_edges);
}